// round 17
// baseline (speedup 1.0000x reference)
#include <cuda_runtime.h>
#include <cuda_fp16.h>
#include <math.h>
#include <stdint.h>

#define B 32
#define C 128
#define L 4096
#define NROW (B*C)
#define BCL (B*C*L)            // 16777216
#define FL 9
#define DIM 512
#define NYL ((size_t)BCL)

// ---------------- scratch (device globals; no allocation) ----------------
__device__ float g_a1[BCL];
__device__ float g_a2[BCL];
__device__ float g_a3[BCL];
__device__ float g_attn[B*(C/4)*L];
__device__ float g_feat[3*B*C];
__device__ float g_h1[B*DIM];
__device__ float g_h2[B*2*DIM];
__device__ __align__(16) uint32_t g_wth[3*12288];   // fp16 MMA weights co 0..63: [lvl][ch8][tap3][co64][p8]
__device__ __align__(16) float    g_wtf[3*24576];   // fp32 FFMA2 weights co 64..127: [lvl][ch8][ci16][tap3][64]
__device__ float g_w2t[2*32*C];                     // attn2 weights [lvl][ci][co]

__device__ __forceinline__ float gelu_f(float x){
    return 0.5f*x*(1.0f+erff(x*0.7071067811865476f));
}
__device__ __forceinline__ float sigmoid_f(float x){
    return 1.0f/(1.0f+expf(-x));
}

// ---- packed f32x2 helpers (Blackwell FFMA2) ----
__device__ __forceinline__ unsigned long long pack2(float lo, float hi){
    unsigned long long r;
    asm("mov.b64 %0, {%1, %2};" : "=l"(r) : "f"(lo), "f"(hi));
    return r;
}
__device__ __forceinline__ unsigned long long fma2(unsigned long long a, unsigned long long b, unsigned long long c){
    unsigned long long d;
    asm("fma.rn.f32x2 %0, %1, %2, %3;" : "=l"(d) : "l"(a), "l"(b), "l"(c));
    return d;
}
__device__ __forceinline__ float2 unpack2(unsigned long long v){
    float2 f;
    asm("mov.b64 {%0, %1}, %2;" : "=f"(f.x), "=f"(f.y) : "l"(v));
    return f;
}

// ---- cp.async + mma helpers (baseline PTX) ----
__device__ __forceinline__ uint32_t smem_u32(const void* p){
    uint32_t a;
    asm("{ .reg .u64 t; cvta.to.shared.u64 t, %1; cvt.u32.u64 %0, t; }" : "=r"(a) : "l"(p));
    return a;
}
__device__ __forceinline__ void cp16(uint32_t dst, const void* src){
    asm volatile("cp.async.ca.shared.global [%0], [%1], 16;" :: "r"(dst), "l"(src) : "memory");
}
__device__ __forceinline__ void cp_commit(){
    asm volatile("cp.async.commit_group;" ::: "memory");
}
template<int N>
__device__ __forceinline__ void cp_wait(){
    asm volatile("cp.async.wait_group %0;" :: "n"(N) : "memory");
}
__device__ __forceinline__ void mma_f16(float* d, uint32_t a0, uint32_t a1, uint32_t a2, uint32_t a3,
                                        uint32_t b0, uint32_t b1){
    asm volatile("mma.sync.aligned.m16n8k16.row.col.f32.f16.f16.f32 "
        "{%0,%1,%2,%3}, {%4,%5,%6,%7}, {%8,%9}, {%0,%1,%2,%3};"
        : "+f"(d[0]), "+f"(d[1]), "+f"(d[2]), "+f"(d[3])
        : "r"(a0), "r"(a1), "r"(a2), "r"(a3), "r"(b0), "r"(b1));
}

// ---------------- mean over L (level 0 only) ----------------
__global__ __launch_bounds__(256) void mean_kernel(const float* __restrict__ x,
                                                   float* __restrict__ feat){
    int row = blockIdx.x;
    const float4* p = (const float4*)(x + (size_t)row*L);
    float s = 0.f;
    for (int i = threadIdx.x; i < L/4; i += 256){
        float4 v = p[i];
        s += (v.x+v.y)+(v.z+v.w);
    }
    __shared__ float red[256];
    red[threadIdx.x] = s; __syncthreads();
    for (int off = 128; off > 0; off >>= 1){
        if (threadIdx.x < off) red[threadIdx.x] += red[threadIdx.x+off];
        __syncthreads();
    }
    if (threadIdx.x == 0) feat[row] = red[0] * (1.0f/(float)L);
}

// ---------------- MLP layers (warp-per-output GEMV) ----------------
__global__ __launch_bounds__(256) void mlp_l1(const float* __restrict__ feat,
                                              const float* __restrict__ sw, const float* __restrict__ sb,
                                              float* __restrict__ h1){
    int b = blockIdx.y;
    int j = blockIdx.x*8 + (threadIdx.x >> 5);
    int lane = threadIdx.x & 31;
    float4 w = ((const float4*)(sw + (size_t)j*C))[lane];
    float4 f = ((const float4*)(feat + b*C))[lane];
    float s = w.x*f.x + w.y*f.y + w.z*f.z + w.w*f.w;
    #pragma unroll
    for (int off = 16; off > 0; off >>= 1) s += __shfl_xor_sync(0xffffffffu, s, off);
    if (lane == 0) h1[b*DIM + j] = gelu_f(s + sb[j]);
}

__global__ __launch_bounds__(256) void mlp_l2(const float* __restrict__ h1,
                                              const float* __restrict__ w1, const float* __restrict__ b1,
                                              float* __restrict__ h2){
    __shared__ __align__(16) float sh[DIM];
    int b = blockIdx.y, t = threadIdx.x;
    for (int i = t; i < DIM/4; i += 256)
        ((float4*)sh)[i] = ((const float4*)(h1 + b*DIM))[i];
    __syncthreads();
    int j = blockIdx.x*8 + (t >> 5);
    int lane = t & 31;
    const float4* wr = (const float4*)(w1 + (size_t)j*DIM);
    float s = 0.f;
    #pragma unroll
    for (int i = 0; i < 4; i++){
        float4 w = wr[i*32 + lane];
        float4 f = ((const float4*)sh)[i*32 + lane];
        s += w.x*f.x + w.y*f.y + w.z*f.z + w.w*f.w;
    }
    #pragma unroll
    for (int off = 16; off > 0; off >>= 1) s += __shfl_xor_sync(0xffffffffu, s, off);
    if (lane == 0) h2[b*2*DIM + j] = gelu_f(s + b1[j]);
}

__global__ __launch_bounds__(576) void mlp_l3(const float* __restrict__ h2,
                                              const float* __restrict__ w2, const float* __restrict__ b2,
                                              float* __restrict__ lo, float* __restrict__ hi){
    __shared__ __align__(16) float sh[2*DIM];
    int b = blockIdx.x, t = threadIdx.x;
    for (int i = t; i < 2*DIM/4; i += 576)
        ((float4*)sh)[i] = ((const float4*)(h2 + b*2*DIM))[i];
    __syncthreads();
    int j = t >> 5, lane = t & 31;
    const float4* wr = (const float4*)(w2 + (size_t)j*2*DIM);
    float s = 0.f;
    #pragma unroll
    for (int i = 0; i < 8; i++){
        float4 w = wr[i*32 + lane];
        float4 f = ((const float4*)sh)[i*32 + lane];
        s += w.x*f.x + w.y*f.y + w.z*f.z + w.w*f.w;
    }
    #pragma unroll
    for (int off = 16; off > 0; off >>= 1) s += __shfl_xor_sync(0xffffffffu, s, off);
    if (lane == 0){
        float v = s + b2[j];
        if (j < FL) lo[b*FL + j] = v;
        else        hi[b*FL + (j-FL)] = v;
    }
}

// ---------------- ortho loss (last level only) + energy=0 ----------------
__global__ void ortho_kernel(const float* __restrict__ lo, float* __restrict__ out_scalars){
    int b = threadIdx.x;
    float v[FL]; float ss = 0.f;
    #pragma unroll
    for (int k = 0; k < FL; k++){ v[k] = lo[b*FL+k]; ss += v[k]*v[k]; }
    float den = sqrtf(ss) + 1e-8f;
    float S = 0.f, sq = 0.f;
    #pragma unroll
    for (int k = 0; k < FL; k++){
        float n = v[k]/den;
        S  += fabsf(n);
        sq += n*n;
    }
    float S2  = S*S;
    float amp = fabsf(sq - 1.0f);
    float sm  = fabsf(v[0]);
    #pragma unroll
    for (int k = 1; k < FL; k++) sm += fabsf(v[k]-v[k-1]);
    sm += fabsf(v[FL-1]);
    #pragma unroll
    for (int off = 16; off > 0; off >>= 1){
        S2  += __shfl_xor_sync(0xffffffffu, S2,  off);
        amp += __shfl_xor_sync(0xffffffffu, amp, off);
        sm  += __shfl_xor_sync(0xffffffffu, sm,  off);
    }
    if (b == 0){
        float shift  = 3.0f * S2 / (32.0f*81.0f);
        float ampm   = amp / 32.0f;
        float smm    = sm / (32.0f*10.0f);
        out_scalars[0] = 0.01f*(shift + ampm) + 0.1f*smm;
        out_scalars[1] = 0.0f;
    }
}

// ---------------- per-sample depthwise 9-tap (edge pad) + mean accumulate ----------------
#define DTL 1024
__global__ __launch_bounds__(256) void dw_kernel(
    const float* __restrict__ x, const float* __restrict__ lo, const float* __restrict__ hi,
    float* __restrict__ out_a, float* __restrict__ out_d, float* __restrict__ feat_next)
{
    int row = blockIdx.y;
    int b   = row >> 7;
    int l0  = blockIdx.x * DTL;
    __shared__ __align__(16) float s[DTL + 16];
    __shared__ float wsum[8];
    const float* xr = x + (size_t)row * L;
    int t = threadIdx.x, lane = t & 31, wid = t >> 5;
    {
        const float4* xv = (const float4*)(xr + l0);
        ((float4*)(s + 4))[t] = xv[t];
    }
    if (t < 4){
        int li = l0 - 4 + t;
        s[t] = xr[max(li, 0)];
        int ri = l0 + DTL + t;
        s[DTL + 4 + t] = xr[min(ri, L-1)];
    }
    unsigned long long pf[FL];
    #pragma unroll
    for (int k = 0; k < FL; k++) pf[k] = pack2(__ldg(&lo[b*FL+k]), __ldg(&hi[b*FL+k]));
    __syncthreads();

    int i0 = t * 4;
    float win[12];
    #pragma unroll
    for (int j = 0; j < 12; j++) win[j] = s[i0 + j];
    unsigned long long acc[4];
    #pragma unroll
    for (int p = 0; p < 4; p++) acc[p] = 0ull;
    #pragma unroll
    for (int k = 0; k < FL; k++){
        #pragma unroll
        for (int p = 0; p < 4; p++){
            unsigned long long vv = pack2(win[p+k], win[p+k]);
            acc[p] = fma2(vv, pf[k], acc[p]);
        }
    }
    float4 ra, rd;
    float2 f0 = unpack2(acc[0]), f1 = unpack2(acc[1]), f2 = unpack2(acc[2]), f3 = unpack2(acc[3]);
    ra.x = f0.x; ra.y = f1.x; ra.z = f2.x; ra.w = f3.x;
    rd.x = f0.y; rd.y = f1.y; rd.z = f2.y; rd.w = f3.y;
    size_t idx = (size_t)row*L + l0 + i0;
    *(float4*)(out_a + idx) = ra;
    *(float4*)(out_d + idx) = rd;

    if (feat_next){
        float s4 = (ra.x + ra.y) + (ra.z + ra.w);
        #pragma unroll
        for (int off = 16; off > 0; off >>= 1) s4 += __shfl_xor_sync(0xffffffffu, s4, off);
        if (lane == 0) wsum[wid] = s4;
        __syncthreads();
        if (t == 0){
            float tot = 0.f;
            #pragma unroll
            for (int w = 0; w < 8; w++) tot += wsum[w];
            atomicAdd(feat_next + row, tot * (1.0f/(float)L));
        }
    }
}

// ---------------- weight prep ----------------
// MMA (co 0..63): g_wth[lvl][ch8][tap3][co64][p8]; p=c4*2+w -> ci = ch*16 + 2*c4 + (w?8:0)
__global__ void wprep_mma(const float* __restrict__ gw, uint32_t* __restrict__ wth){
    int idx = blockIdx.x*256 + threadIdx.x;
    if (idx < 3*12288){
        int lvl = idx / 12288;
        int r   = idx % 12288;
        int ch  = r / 1536;
        int r2  = r % 1536;
        int tap = r2 / 512;
        int q   = r2 % 512;
        int co  = q >> 3;
        int p   = q & 7;
        int c4 = p >> 1, w = p & 1;
        int ci  = ch*16 + 2*c4 + (w ? 8 : 0);
        float f0 = gw[(((size_t)lvl*C + co)*C + ci)*3 + tap];
        float f1 = gw[(((size_t)lvl*C + co)*C + ci + 1)*3 + tap];
        __half2 h2 = __floats2half2_rn(f0, f1);
        wth[idx] = *(const uint32_t*)&h2;
    }
}
// FFMA2 (co 64..127): g_wtf[lvl][ch8][ci16][tap3][64]
__global__ void wprep_ffma(const float* __restrict__ gw, float* __restrict__ wtf){
    int idx = blockIdx.x*256 + threadIdx.x;
    if (idx < 3*24576){
        int lvl = idx / 24576;
        int r   = idx % 24576;
        int ch  = r / 3072;
        int r2  = r % 3072;
        int cil = r2 / 192;
        int r3  = r2 % 192;
        int tap = r3 / 64;
        int cof = r3 % 64;
        int ci  = ch*16 + cil;
        int co  = 64 + cof;
        wtf[idx] = gw[(((size_t)lvl*C + co)*C + ci)*3 + tap];
    }
}
__global__ void prep2_kernel(const float* __restrict__ attn2_w, float* __restrict__ w2t,
                             float* __restrict__ feat){
    int idx = blockIdx.x*256 + threadIdx.x;
    if (idx < 2*32*C){
        int lvl = idx / (32*C);
        int r   = idx % (32*C);
        int ci  = r >> 7, co = r & 127;
        w2t[idx] = attn2_w[((size_t)lvl*C + co)*32 + ci];
    }
    if (idx < 2*B*C) feat[B*C + idx] = 0.f;
}

// ---------------- fused gates: dual-pipe conv3 + attn2 (phase1) + attn1 (phase3) ----
// s_xh[r][ci] fp16, r = l_local + 1, pitch PH=138 halves (PHW=69 words, odd -> column reads conflict-free)
#define PH  138
#define PHW 69
#define SO_MW 35904                     // 130*138*2 = 35880, padded
#define MCH_B 6144                      // MMA chunk: [tap3][co64][8] u32
#define SO_FW (SO_MW + 2*MCH_B)         // 48192
#define FCH_B 12288                     // FFMA2 chunk: [ci16][tap3][64] f32
#define SO_W2 (SO_FW + 2*FCH_B)         // 72768
#define SO_W1 (SO_W2 + 16384)           // 89152
#define GSM_TT (SO_W1 + 16384)          // 105536 (ATTN + A1)
#define GSM_SM 89152                    // other variants

template<bool ATTN, bool A1>
__global__ __launch_bounds__(256, 2) void gatesf_kernel(
    const float* __restrict__ cur, const float* __restrict__ det_raw,
    const uint32_t* __restrict__ wth, const float* __restrict__ wtf, const float* __restrict__ bias,
    const float* __restrict__ a_in, const float* __restrict__ w2t, const float* __restrict__ bias2,
    float* __restrict__ yh_out, float* __restrict__ out,
    const float* __restrict__ w1, const float* __restrict__ b1, float* __restrict__ a_out)
{
    extern __shared__ __align__(16) char smem[];
    __half* s_xh = (__half*)smem;            // [130][PH]
    float*  s_w2 = (float*)(smem + SO_W2);
    float*  s_w1 = (float*)(smem + (ATTN ? SO_W1 : SO_W2));
    uint32_t mw_base = smem_u32(smem + SO_MW);
    uint32_t fw_base = smem_u32(smem + SO_FW);
    int l0 = blockIdx.x*128, b = blockIdx.y, t = threadIdx.x;
    int wid = t >> 5, lane = t & 31;
    int g = lane >> 2, c4 = lane & 3;

    // prologue prefetch chunk 0 (both rings, one group)
    {
        const char* msrc = (const char*)wth;
        for (int o = t*16; o < MCH_B; o += 4096) cp16(mw_base + o, msrc + o);
        const char* fsrc = (const char*)wtf;
        for (int o = t*16; o < FCH_B; o += 4096) cp16(fw_base + o, fsrc + o);
        cp_commit();
    }

    // ---- fill s_xh transposed fp16 ----
    #pragma unroll 4
    for (int k = 0; k < 16; k++){
        int idx4 = t + k*256;
        int ci = idx4 >> 5, j4 = (idx4 & 31)*4;
        float4 v = *(const float4*)(cur + ((size_t)(b*C+ci))*L + l0 + j4);
        s_xh[(j4+1)*PH + ci] = __float2half(v.x);
        s_xh[(j4+2)*PH + ci] = __float2half(v.y);
        s_xh[(j4+3)*PH + ci] = __float2half(v.z);
        s_xh[(j4+4)*PH + ci] = __float2half(v.w);
    }
    {
        int ci = t & 127;
        size_t row = (size_t)(b*C+ci)*L;
        if (t < 128){
            float v = (l0 > 0) ? cur[row + l0 - 1] : 0.f;
            s_xh[ci] = __float2half(v);
        } else {
            float v = (l0 + 128 < L) ? cur[row + l0 + 128] : 0.f;
            s_xh[129*PH + ci] = __float2half(v);
        }
    }
    if (ATTN){
        for (int idx = t; idx < 32*C; idx += 256) s_w2[idx] = w2t[idx];
    }
    if (A1){
        for (int idx = t; idx < 32*C; idx += 256){
            int ci = idx >> 5, c2 = idx & 31;
            s_w1[idx] = w1[c2*C + ci];
        }
    }
    __syncthreads();

    // ---- phase 1 (ATTN): det' = det*(1+sig(W2*a+b2)) -> yh_out, 2 half-passes ----
    if (ATTN){
        int co0 = wid*16, lq = lane*4;
        #pragma unroll 1
        for (int half = 0; half < 2; half++){
            unsigned long long acc2[4][4];
            #pragma unroll
            for (int c = 0; c < 4; c++)
                #pragma unroll
                for (int q = 0; q < 4; q++) acc2[c][q] = 0ull;
            #pragma unroll 4
            for (int ci = 0; ci < 32; ci++){
                float4 xv = *(const float4*)(a_in + ((size_t)(b*32+ci))*L + l0 + lq);
                unsigned long long p0 = pack2(xv.x, xv.x);
                unsigned long long p1 = pack2(xv.y, xv.y);
                unsigned long long p2 = pack2(xv.z, xv.z);
                unsigned long long p3 = pack2(xv.w, xv.w);
                const ulonglong2* wp = (const ulonglong2*)(&s_w2[ci*C + co0 + half*8]);
                unsigned long long wr[4];
                ((ulonglong2*)wr)[0] = wp[0];
                ((ulonglong2*)wr)[1] = wp[1];
                #pragma unroll
                for (int c = 0; c < 4; c++){
                    acc2[c][0] = fma2(wr[c], p0, acc2[c][0]);
                    acc2[c][1] = fma2(wr[c], p1, acc2[c][1]);
                    acc2[c][2] = fma2(wr[c], p2, acc2[c][2]);
                    acc2[c][3] = fma2(wr[c], p3, acc2[c][3]);
                }
            }
            #pragma unroll
            for (int c = 0; c < 4; c++){
                int co = co0 + half*8 + 2*c;
                float2 z[4];
                #pragma unroll
                for (int q = 0; q < 4; q++) z[q] = unpack2(acc2[c][q]);
                #pragma unroll
                for (int s = 0; s < 2; s++){
                    float bv = __ldg(&bias2[co+s]);
                    size_t idx = ((size_t)(b*C+co+s))*L + l0 + lq;
                    float4 dv = *(const float4*)(det_raw + idx);
                    dv.x *= 1.0f + sigmoid_f((s ? z[0].y : z[0].x) + bv);
                    dv.y *= 1.0f + sigmoid_f((s ? z[1].y : z[1].x) + bv);
                    dv.z *= 1.0f + sigmoid_f((s ? z[2].y : z[2].x) + bv);
                    dv.w *= 1.0f + sigmoid_f((s ? z[3].y : z[3].x) + bv);
                    *(float4*)(yh_out + idx) = dv;
                }
            }
        }
    }

    // ---- phase 2: dual-pipe mainloop, 8 chunks of 16 ci ----
    // MMA warps (0-3): co 0..63.  FFMA2 warps (4-7): co 64..127.
    float d[2][8][4];                  // MMA accumulators (warps 0-3)
    unsigned long long accf[8][4];     // FFMA2 accumulators (warps 4-7)
    if (wid < 4){
        #pragma unroll
        for (int mi = 0; mi < 2; mi++)
            #pragma unroll
            for (int ni = 0; ni < 8; ni++)
                #pragma unroll
                for (int r = 0; r < 4; r++) d[mi][ni][r] = 0.f;
    } else {
        #pragma unroll
        for (int c = 0; c < 8; c++)
            #pragma unroll
            for (int q = 0; q < 4; q++) accf[c][q] = 0ull;
    }

    const uint32_t* sxh_u = (const uint32_t*)smem;
    int co_m = (wid & 1)*32;           // MMA warp co base
    int n0   = ((wid >> 1)&1)*64;      // MMA warp l base
    int w4   = wid - 4;                // FFMA2 warp index

    for (int ch = 0; ch < 8; ch++){
        if (ch) __syncthreads();                          // prev chunk compute done
        if (ch < 7){
            int nc = ch + 1, slot = nc & 1;
            const char* msrc = (const char*)wth + (size_t)nc*MCH_B;
            for (int o = t*16; o < MCH_B; o += 4096) cp16(mw_base + slot*MCH_B + o, msrc + o);
            const char* fsrc = (const char*)wtf + (size_t)nc*FCH_B;
            for (int o = t*16; o < FCH_B; o += 4096) cp16(fw_base + slot*FCH_B + o, fsrc + o);
            cp_commit();
            cp_wait<1>();
        } else {
            cp_wait<0>();
        }
        __syncthreads();                                  // chunk ch visible

        if (wid < 4){
            // ---- MMA path: 3 taps x k16 over this chunk's 16 ci ----
            const uint32_t* wch = (const uint32_t*)(smem + SO_MW + (ch&1)*MCH_B);
            int cw0 = ch*8;
            #pragma unroll
            for (int tap = 0; tap < 3; tap++){
                uint32_t af[2][4];
                #pragma unroll
                for (int mi = 0; mi < 2; mi++){
                    int co = co_m + mi*16 + g;
                    unsigned long long w0 = *(const unsigned long long*)(wch + tap*512 + co*8     + c4*2);
                    unsigned long long w8 = *(const unsigned long long*)(wch + tap*512 + (co+8)*8 + c4*2);
                    af[mi][0] = (uint32_t)w0;
                    af[mi][2] = (uint32_t)(w0 >> 32);
                    af[mi][1] = (uint32_t)w8;
                    af[mi][3] = (uint32_t)(w8 >> 32);
                }
                int r0 = n0 + g + tap;
                const uint32_t* xb = sxh_u + r0*PHW + cw0 + c4;
                #pragma unroll
                for (int ni = 0; ni < 8; ni++){
                    uint32_t b0v = xb[ni*8*PHW];
                    uint32_t b1v = xb[ni*8*PHW + 4];
                    mma_f16(d[0][ni], af[0][0], af[0][1], af[0][2], af[0][3], b0v, b1v);
                    mma_f16(d[1][ni], af[1][0], af[1][1], af[1][2], af[1][3], b0v, b1v);
                }
            }
        } else {
            // ---- FFMA2 path: 16 ci x 3 taps, co 64..127 ----
            const float* wf = (const float*)(smem + SO_FW + (ch&1)*FCH_B);
            int cwoff = w4*16;     // co offset within [64..127]
            #pragma unroll 2
            for (int cil = 0; cil < 16; cil++){
                int ci = ch*16 + cil;
                float xv[4][3];
                #pragma unroll
                for (int q = 0; q < 4; q++){
                    int rb = lane + 32*q;
                    xv[q][0] = __half2float(s_xh[rb*PH + ci]);
                    xv[q][1] = __half2float(s_xh[(rb+1)*PH + ci]);
                    xv[q][2] = __half2float(s_xh[(rb+2)*PH + ci]);
                }
                #pragma unroll
                for (int tap = 0; tap < 3; tap++){
                    const ulonglong2* wp = (const ulonglong2*)(&wf[(cil*3+tap)*64 + cwoff]);
                    unsigned long long wr[8];
                    ((ulonglong2*)wr)[0] = wp[0];
                    ((ulonglong2*)wr)[1] = wp[1];
                    ((ulonglong2*)wr)[2] = wp[2];
                    ((ulonglong2*)wr)[3] = wp[3];
                    #pragma unroll
                    for (int q = 0; q < 4; q++){
                        unsigned long long p = pack2(xv[q][tap], xv[q][tap]);
                        #pragma unroll
                        for (int c = 0; c < 8; c++)
                            accf[c][q] = fma2(wr[c], p, accf[c][q]);
                    }
                }
            }
        }
    }
    __syncthreads();     // all s_xh reads done before A1 restage

    // ---- epilogue ----
    const float* dsrc = ATTN ? yh_out : det_raw;
    if (wid < 4){
        #pragma unroll
        for (int mi = 0; mi < 2; mi++){
            #pragma unroll
            for (int half = 0; half < 2; half++){
                int co = co_m + mi*16 + g + half*8;
                float bv = __ldg(&bias[co]);
                size_t rowg = ((size_t)(b*C+co))*L + l0;
                #pragma unroll
                for (int ni = 0; ni < 8; ni++){
                    int l = n0 + ni*8 + c4*2;
                    float z0 = d[mi][ni][half*2 + 0];
                    float z1 = d[mi][ni][half*2 + 1];
                    float2 cv = *(const float2*)(cur + rowg + l);
                    float2 dv = *(const float2*)(dsrc + rowg + l);
                    float o0 = cv.x + sigmoid_f(z0 + bv)*dv.x;
                    float o1 = cv.y + sigmoid_f(z1 + bv)*dv.y;
                    *(float2*)(out + rowg + l) = make_float2(o0, o1);
                    if (A1){
                        s_xh[(l+1)*PH + co] = __float2half(o0);
                        s_xh[(l+2)*PH + co] = __float2half(o1);
                    }
                }
            }
        }
    } else {
        #pragma unroll
        for (int c = 0; c < 8; c++){
            int co = 64 + w4*16 + 2*c;
            float b0v = __ldg(&bias[co]);
            float b1v = __ldg(&bias[co+1]);
            size_t row0 = ((size_t)(b*C+co))*L + l0;
            size_t row1 = row0 + L;
            #pragma unroll
            for (int q = 0; q < 4; q++){
                int l = lane + 32*q;
                float2 z = unpack2(accf[c][q]);
                float c0 = cur[row0 + l], c1 = cur[row1 + l];
                float d0 = dsrc[row0 + l], d1 = dsrc[row1 + l];
                float o0 = c0 + sigmoid_f(z.x + b0v)*d0;
                float o1 = c1 + sigmoid_f(z.y + b1v)*d1;
                out[row0 + l] = o0;
                out[row1 + l] = o1;
                if (A1){
                    s_xh[(l+1)*PH + co]     = __float2half(o0);
                    s_xh[(l+1)*PH + co + 1] = __float2half(o1);
                }
            }
        }
    }

    // ---- phase 3 (A1): a_out = gelu(W1*out + b1), out read from s_xh (fp16) ----
    if (A1){
        __syncthreads();
        int c2b = wid*4;
        unsigned long long acc3[2][4];
        #pragma unroll
        for (int pc = 0; pc < 2; pc++)
            #pragma unroll
            for (int q = 0; q < 4; q++) acc3[pc][q] = 0ull;
        #pragma unroll 2
        for (int ci2 = 0; ci2 < 64; ci2++){
            ulonglong2 wvA = *(const ulonglong2*)(&s_w1[(2*ci2)*32 + c2b]);
            ulonglong2 wvB = *(const ulonglong2*)(&s_w1[(2*ci2+1)*32 + c2b]);
            #pragma unroll
            for (int q = 0; q < 4; q++){
                uint32_t xv = sxh_u[(lane + 32*q + 1)*PHW + ci2];
                float2 xf = __half22float2(*(const __half2*)&xv);
                unsigned long long p0 = pack2(xf.x, xf.x);
                unsigned long long p1 = pack2(xf.y, xf.y);
                acc3[0][q] = fma2(wvA.x, p0, acc3[0][q]);
                acc3[0][q] = fma2(wvB.x, p1, acc3[0][q]);
                acc3[1][q] = fma2(wvA.y, p0, acc3[1][q]);
                acc3[1][q] = fma2(wvB.y, p1, acc3[1][q]);
            }
        }
        #pragma unroll
        for (int pc = 0; pc < 2; pc++){
            int c2 = c2b + 2*pc;
            float b10 = __ldg(&b1[c2]);
            float b11 = __ldg(&b1[c2+1]);
            #pragma unroll
            for (int q = 0; q < 4; q++){
                float2 z = unpack2(acc3[pc][q]);
                size_t ix = ((size_t)(b*32 + c2))*L + l0 + lane + 32*q;
                a_out[ix]     = gelu_f(z.x + b10);
                a_out[ix + L] = gelu_f(z.y + b11);
            }
        }
    }
}

// ---------------- host launch ----------------
extern "C" void kernel_launch(void* const* d_in, const int* in_sizes, int n_in,
                              void* d_out, int out_size)
{
    const float* x       = (const float*)d_in[0];
    const float* stat_w  = (const float*)d_in[1];
    const float* stat_b  = (const float*)d_in[2];
    const float* wg1_w   = (const float*)d_in[3];
    const float* wg1_b   = (const float*)d_in[4];
    const float* wg2_w   = (const float*)d_in[5];
    const float* wg2_b   = (const float*)d_in[6];
    const float* gates_w = (const float*)d_in[7];
    const float* gates_b = (const float*)d_in[8];
    const float* attn1_w = (const float*)d_in[9];
    const float* attn1_b = (const float*)d_in[10];
    const float* attn2_w = (const float*)d_in[11];
    const float* attn2_b = (const float*)d_in[12];
    float* out = (float*)d_out;

    float *a1, *a2, *a3, *attn, *feat, *h1, *h2, *w2t, *wtf;
    uint32_t *wth;
    cudaGetSymbolAddress((void**)&a1,   g_a1);
    cudaGetSymbolAddress((void**)&a2,   g_a2);
    cudaGetSymbolAddress((void**)&a3,   g_a3);
    cudaGetSymbolAddress((void**)&attn, g_attn);
    cudaGetSymbolAddress((void**)&feat, g_feat);
    cudaGetSymbolAddress((void**)&h1,   g_h1);
    cudaGetSymbolAddress((void**)&h2,   g_h2);
    cudaGetSymbolAddress((void**)&wth,  g_wth);
    cudaGetSymbolAddress((void**)&wtf,  g_wtf);
    cudaGetSymbolAddress((void**)&w2t,  g_w2t);

    float* yl  = out;
    float* yh0 = out + NYL;
    float* yh1 = out + 2*NYL;
    float* yh2 = out + 3*NYL;
    float* scal= out + 4*NYL;
    float* lo_all = out + 4*NYL + 2;
    float* hi_all = lo_all + 3*B*FL;

    cudaFuncSetAttribute((const void*)gatesf_kernel<false,true>,  cudaFuncAttributeMaxDynamicSharedMemorySize, GSM_SM);
    cudaFuncSetAttribute((const void*)gatesf_kernel<true,true>,   cudaFuncAttributeMaxDynamicSharedMemorySize, GSM_TT);
    cudaFuncSetAttribute((const void*)gatesf_kernel<true,false>,  cudaFuncAttributeMaxDynamicSharedMemorySize, GSM_SM);

    wprep_mma<<<(3*12288 + 255)/256, 256>>>(gates_w, wth);
    wprep_ffma<<<(3*24576 + 255)/256, 256>>>(gates_w, wtf);
    prep2_kernel<<<(2*32*C + 255)/256, 256>>>(attn2_w, w2t, feat);

    const float* ain[3]  = {x, a1, a2};
    float*       aout[3] = {a1, a2, a3};
    float*       dets[3] = {yh0, yh1, yh2};

    mean_kernel<<<NROW, 256>>>(x, feat);
    for (int lvl = 0; lvl < 3; lvl++){
        float* lo = lo_all + lvl*B*FL;
        float* hi = hi_all + lvl*B*FL;
        const float* f = feat + lvl*B*C;
        mlp_l1<<<dim3(DIM/8, B), 256>>>(f, stat_w, stat_b, h1);
        mlp_l2<<<dim3(2*DIM/8, B), 256>>>(h1, wg1_w, wg1_b, h2);
        mlp_l3<<<B, 576>>>(h2, wg2_w, wg2_b, lo, hi);
        float* fnext = (lvl < 2) ? (feat + (lvl+1)*B*C) : nullptr;
        dw_kernel<<<dim3(L/DTL, NROW), 256>>>(ain[lvl], lo, hi, aout[lvl], dets[lvl], fnext);
    }

    ortho_kernel<<<1, 32>>>(lo_all + 2*B*FL, scal);

    // i = 2: gates (no attn2) + fused attn1 for level 1 -> attn
    gatesf_kernel<false,true><<<dim3(L/128, B), 256, GSM_SM>>>(
        a3, yh2, wth + 2*12288, wtf + 2*24576, gates_b + 2*C,
        nullptr, nullptr, nullptr, nullptr, a1,
        attn1_w + 1*(C/4)*C, attn1_b + (C/4), attn);
    // i = 1: gates + attn2(level 1) + fused attn1 for level 0 -> attn
    gatesf_kernel<true,true><<<dim3(L/128, B), 256, GSM_TT>>>(
        a1, yh1, wth + 1*12288, wtf + 1*24576, gates_b + 1*C,
        attn, w2t + 32*C, attn2_b + C, yh1, a2,
        attn1_w, attn1_b, attn);
    // i = 0: gates + attn2(level 0) -> yl
    gatesf_kernel<true,false><<<dim3(L/128, B), 256, GSM_SM>>>(
        a2, yh0, wth, wtf, gates_b,
        attn, w2t, attn2_b, yh0, yl,
        nullptr, nullptr, nullptr);
}